// round 8
// baseline (speedup 1.0000x reference)
#include <cuda_runtime.h>
#include <cuda_bf16.h>

typedef unsigned long long u64;
typedef unsigned int u32;

#define NBATCH 512
#define NTT    257
#define NIVL   256
#define NIN    32
#define NH     128
#define NBN    256
#define NOUT   64
#define GRID_CTAS 128
#define TPB    256

// ---- shared memory byte offsets ----
#define SM_FRAGB 0          // [16 kt][16 nt][32 lane] uint4 (bhi0,bhi1,blo0,blo1) = 128KB
#define SM_W1    131072     // [128][8] f32
#define SM_W2    135168     // [256][8] f32
#define SM_B3    143360     // [128] f32
#define SM_B1    143872     // [8]
#define SM_B2    143904     // [8]
#define SM_MW    143936     // [128][2]
#define SM_SW    144960     // [128][2]
#define SM_MB    145984     // [2]
#define SM_SB    145992     // [2] (+pad)
#define SM_DX    146016     // [128][33] f32
#define SM_ACT   162912     // 2 x 4096 f32 stage-1/2 staging
#define SMEM_BYTES 195680

// ---- global scratch ----
__device__ float g_zc[2][4 * NH * 128];    // col-major [h][r] per bb
__device__ float g_h1[2][4 * NBN * 128];   // col-major [c][r] per bb
// h2 exchanged as mma A-fragments: [parity][bb][ (kt*8+mt)*32+lane ] uint4 (a0..a3)
__device__ uint4 g_fAhi[2][4][4096];
__device__ uint4 g_fAlo[2][4][4096];

// ---- quarter arrive counters: [bb][quarter], one padded line each ----
struct PadCnt { unsigned v; unsigned pad[127]; };   // 512B stride
__device__ PadCnt g_qz[4][4];
__device__ PadCnt g_q1[4][4];
__device__ PadCnt g_q2[4][4];

struct PadU { unsigned v; unsigned pad[31]; };
__device__ PadU g_cnt[4];
__device__ PadU g_rel[4];

// ---- f32x2 helpers (stage 1/2 SIMT GEMM) ----
__device__ __forceinline__ u64 pack2(float x, float y) {
    u64 r;
    asm("mov.b64 %0, {%1, %2};" : "=l"(r) : "f"(x), "f"(y));
    return r;
}
__device__ __forceinline__ float2 unpack2(u64 v) {
    float2 r;
    asm("mov.b64 {%0, %1}, %2;" : "=f"(r.x), "=f"(r.y) : "l"(v));
    return r;
}
__device__ __forceinline__ void fma2(u64& d, u64 a, u64 b) {
    asm("fma.rn.f32x2 %0, %1, %2, %0;" : "+l"(d) : "l"(a), "l"(b));
}

__device__ __forceinline__ float fast_tanh(float x) {
    float e;
    asm("ex2.approx.f32 %0, %1;" : "=f"(e) : "f"(x * 2.8853900817779268f));
    float r;
    asm("rcp.approx.f32 %0, %1;" : "=f"(r) : "f"(e + 1.0f));
    return fmaf(-2.0f, r, 1.0f);
}
__device__ __forceinline__ float softplus_f(float x) {
    return fmaxf(x, 0.0f) + log1pf(expf(-fabsf(x)));
}

// ---- mma.sync m16n8k16 row.col f32.bf16.bf16.f32 ----
__device__ __forceinline__ void mma16816(float* c, uint4 a, u32 b0, u32 b1) {
    asm volatile(
        "mma.sync.aligned.m16n8k16.row.col.f32.bf16.bf16.f32 "
        "{%0,%1,%2,%3}, {%4,%5,%6,%7}, {%8,%9}, {%0,%1,%2,%3};"
        : "+f"(c[0]), "+f"(c[1]), "+f"(c[2]), "+f"(c[3])
        : "r"(a.x), "r"(a.y), "r"(a.z), "r"(a.w), "r"(b0), "r"(b1));
}

__device__ __forceinline__ void bf_split(float x, unsigned short& h, unsigned short& l) {
    __nv_bfloat16 bh = __float2bfloat16_rn(x);
    __nv_bfloat16 bl = __float2bfloat16_rn(x - __bfloat162float(bh));
    h = __bfloat16_as_ushort(bh);
    l = __bfloat16_as_ushort(bl);
}

// ---- counter publish / wait ----
__device__ __forceinline__ void publish_cnt(PadCnt* c) {
    __syncthreads();
    if (threadIdx.x == 0) {
        asm volatile("red.release.gpu.global.add.u32 [%0], %1;"
                     :: "l"(&c->v), "r"(1u) : "memory");
    }
}
__device__ __forceinline__ void wait_cnt(PadCnt* c, unsigned target) {
    if (threadIdx.x == 0) {
        unsigned v;
        do {
            asm volatile("ld.acquire.gpu.u32 %0, [%1];"
                         : "=r"(v) : "l"(&c->v) : "memory");
        } while ((int)(v - target) < 0);
    }
    __syncthreads();
}

// ---- legacy group barrier (end-of-kernel reset only) ----
__device__ __forceinline__ void gbar_val(int grp, unsigned target) {
    __syncthreads();
    if (threadIdx.x == 0) {
        __threadfence();
        unsigned old = atomicAdd(&g_cnt[grp].v, 1u);
        if (old == 31u) {
            g_cnt[grp].v = 0u;
            asm volatile("st.release.gpu.u32 [%0], %1;"
                         :: "l"(&g_rel[grp].v), "r"(target) : "memory");
        } else {
            unsigned v;
            do {
                asm volatile("ld.acquire.gpu.u32 %0, [%1];"
                             : "=r"(v) : "l"(&g_rel[grp].v) : "memory");
            } while (v != target);
        }
    }
    __syncthreads();
}

// ---- stage 1: h1[8 cols col-major] = relu(z @ W1slice + b1); chunked waits ----
__device__ __forceinline__ void stage1(const float* __restrict__ gin_cm,
                                       const float* __restrict__ sW,
                                       const float* __restrict__ sb,
                                       float* __restrict__ gout_cm,
                                       float* __restrict__ sAct, int tid,
                                       PadCnt* qc, unsigned tgt) {
    const int r  = tid & 127;
    const int ch = tid >> 7;
    u64 acc0 = pack2(sb[ch * 4 + 0], sb[ch * 4 + 1]);
    u64 acc1 = pack2(sb[ch * 4 + 2], sb[ch * 4 + 3]);

    const float4* src = (const float4*)gin_cm;
    wait_cnt(&qc[0], tgt);
    float4 v0 = __ldcg(src + 0 * 256 + tid);
    float4 v1 = __ldcg(src + 1 * 256 + tid);
    float4 v2 = __ldcg(src + 2 * 256 + tid);
    float4 v3 = __ldcg(src + 3 * 256 + tid);

#pragma unroll 1
    for (int kc = 0; kc < 4; kc++) {
        float4* buf4 = (float4*)(sAct + (kc & 1) * 4096);
        buf4[0 * 256 + tid] = v0;
        buf4[1 * 256 + tid] = v1;
        buf4[2 * 256 + tid] = v2;
        buf4[3 * 256 + tid] = v3;
        __syncthreads();
        if (kc + 1 < 4) {
            wait_cnt(&qc[kc + 1], tgt);       // z quarter kc+1 = h cols [32(kc+1)..)
            const float4* sn = src + (kc + 1) * 1024;
            v0 = __ldcg(sn + 0 * 256 + tid);
            v1 = __ldcg(sn + 1 * 256 + tid);
            v2 = __ldcg(sn + 2 * 256 + tid);
            v3 = __ldcg(sn + 3 * 256 + tid);
        }
        const float* buf = sAct + (kc & 1) * 4096;
        const float* wk  = sW + kc * 32 * 8 + ch * 4;
#pragma unroll
        for (int k = 0; k < 32; k++) {
            float a = buf[k * 128 + r];
            u64 aa  = pack2(a, a);
            ulonglong2 w = *(const ulonglong2*)(wk + k * 8);
            fma2(acc0, aa, w.x);
            fma2(acc1, aa, w.y);
        }
        __syncthreads();
    }
    float2 u0 = unpack2(acc0), u1 = unpack2(acc1);
    __stcg(gout_cm + (ch * 4 + 0) * 128 + r, fmaxf(u0.x, 0.f));
    __stcg(gout_cm + (ch * 4 + 1) * 128 + r, fmaxf(u0.y, 0.f));
    __stcg(gout_cm + (ch * 4 + 2) * 128 + r, fmaxf(u1.x, 0.f));
    __stcg(gout_cm + (ch * 4 + 3) * 128 + r, fmaxf(u1.y, 0.f));
}

// ---- stage 2: h2 cols -> bf16 hi/lo mma A-fragments in gmem; chunked waits ----
__device__ __forceinline__ void stage2_frag(const float* __restrict__ gin_cm,
                                            const float* __restrict__ sW,
                                            const float* __restrict__ sb,
                                            u32* __restrict__ fHi,
                                            u32* __restrict__ fLo,
                                            int g, float* __restrict__ sAct, int tid,
                                            PadCnt* qc, unsigned tgt) {
    const int r  = tid & 127;
    const int ch = tid >> 7;
    u64 acc0 = pack2(sb[ch * 4 + 0], sb[ch * 4 + 1]);
    u64 acc1 = pack2(sb[ch * 4 + 2], sb[ch * 4 + 3]);

    const float4* src = (const float4*)gin_cm;
    wait_cnt(&qc[0], tgt);
    float4 v0 = __ldcg(src + 0 * 256 + tid);
    float4 v1 = __ldcg(src + 1 * 256 + tid);
    float4 v2 = __ldcg(src + 2 * 256 + tid);
    float4 v3 = __ldcg(src + 3 * 256 + tid);

#pragma unroll 1
    for (int kc = 0; kc < 8; kc++) {
        float4* buf4 = (float4*)(sAct + (kc & 1) * 4096);
        buf4[0 * 256 + tid] = v0;
        buf4[1 * 256 + tid] = v1;
        buf4[2 * 256 + tid] = v2;
        buf4[3 * 256 + tid] = v3;
        __syncthreads();
        if (kc + 1 < 8) {
            if (((kc + 1) & 1) == 0)
                wait_cnt(&qc[(kc + 1) >> 1], tgt);  // h1 quarter = 64 cols
            const float4* sn = src + (kc + 1) * 1024;
            v0 = __ldcg(sn + 0 * 256 + tid);
            v1 = __ldcg(sn + 1 * 256 + tid);
            v2 = __ldcg(sn + 2 * 256 + tid);
            v3 = __ldcg(sn + 3 * 256 + tid);
        }
        const float* buf = sAct + (kc & 1) * 4096;
        const float* wk  = sW + kc * 32 * 8 + ch * 4;
#pragma unroll
        for (int k = 0; k < 32; k++) {
            float a = buf[k * 128 + r];
            u64 aa  = pack2(a, a);
            ulonglong2 w = *(const ulonglong2*)(wk + k * 8);
            fma2(acc0, aa, w.x);
            fma2(acc1, aa, w.y);
        }
        __syncthreads();
    }
    float2 u0 = unpack2(acc0), u1 = unpack2(acc1);
    float o0 = fmaxf(u0.x, 0.f), o1 = fmaxf(u0.y, 0.f);
    float o2 = fmaxf(u1.x, 0.f), o3 = fmaxf(u1.y, 0.f);

    unsigned short h0, h1, h2, h3, l0, l1, l2, l3;
    bf_split(o0, h0, l0); bf_split(o1, h1, l1);
    bf_split(o2, h2, l2); bf_split(o3, h3, l3);
    u32 hi01 = ((u32)h1 << 16) | h0;
    u32 hi23 = ((u32)h3 << 16) | h2;
    u32 lo01 = ((u32)l1 << 16) | l0;
    u32 lo23 = ((u32)l3 << 16) | l2;

    const int kt   = g >> 1;
    const int mt   = r >> 4;
    const int lane = (r & 7) * 4 + 2 * ch;
    const int reg  = ((r >> 3) & 1) + 2 * (g & 1);
    const int idx0 = ((kt * 8 + mt) * 32 + lane) * 4 + reg;
    __stcg(&fHi[idx0], hi01);
    __stcg(&fHi[idx0 + 4], hi23);
    __stcg(&fLo[idx0], lo01);
    __stcg(&fLo[idx0 + 4], lo23);
}

// ================= persistent kernel =================
__global__ void __launch_bounds__(TPB, 1)
cde_persistent(const float* __restrict__ t, const float* __restrict__ z0,
               const float* __restrict__ X,
               const float* __restrict__ W1, const float* __restrict__ b1,
               const float* __restrict__ W2, const float* __restrict__ b2,
               const float* __restrict__ W3, const float* __restrict__ b3,
               const float* __restrict__ mW, const float* __restrict__ mb,
               const float* __restrict__ sWp, const float* __restrict__ sbp,
               float* __restrict__ out) {
    extern __shared__ char smb[];
    uint4* sFragB = (uint4*)(smb + SM_FRAGB);
    float* sW1  = (float*)(smb + SM_W1);
    float* sW2  = (float*)(smb + SM_W2);
    float* sb3  = (float*)(smb + SM_B3);
    float* sb1  = (float*)(smb + SM_B1);
    float* sb2  = (float*)(smb + SM_B2);
    float* smW  = (float*)(smb + SM_MW);
    float* ssW  = (float*)(smb + SM_SW);
    float* smb_ = (float*)(smb + SM_MB);
    float* ssb  = (float*)(smb + SM_SB);
    float* sDx  = (float*)(smb + SM_DX);
    float* sAct = (float*)(smb + SM_ACT);

    const int tid  = threadIdx.x;
    const int wid  = tid >> 5;
    const int lane = tid & 31;
    const int bb   = blockIdx.x >> 5;
    const int g    = blockIdx.x & 31;
    const int rowBase = bb * 128;

    PadCnt* qz = &g_qz[bb][0];
    PadCnt* q1 = &g_q1[bb][0];
    PadCnt* q2 = &g_q2[bb][0];
    PadCnt* myQz = &g_qz[bb][g >> 3];
    PadCnt* myQ1 = &g_q1[bb][g >> 3];
    PadCnt* myQ2 = &g_q2[bb][g >> 3];

    // ---- init: W3 slice -> B fragments (hi/lo) in smem ----
    for (int i = tid; i < 16 * 16 * 32; i += TPB) {
        int ln = i & 31, nt = (i >> 5) & 15, kt = i >> 9;
        int nl = nt * 8 + (ln >> 2);
        int k0 = kt * 16 + (ln & 3) * 2;
        const float* wp = W3 + (size_t)k0 * 4096 + g * 128 + nl;
        unsigned short h0, h1, h8, h9, l0, l1, l8, l9;
        bf_split(wp[0],          h0, l0);
        bf_split(wp[4096],       h1, l1);
        bf_split(wp[8 * 4096],   h8, l8);
        bf_split(wp[9 * 4096],   h9, l9);
        uint4 v;
        v.x = ((u32)h1 << 16) | h0;
        v.y = ((u32)h9 << 16) | h8;
        v.z = ((u32)l1 << 16) | l0;
        v.w = ((u32)l9 << 16) | l8;
        sFragB[i] = v;
    }
    for (int i = tid; i < 128 * 2; i += TPB) {
        int k = i >> 1, c4 = i & 1;
        *(float4*)(sW1 + k * 8 + c4 * 4) =
            __ldg((const float4*)(W1 + (size_t)k * 256 + g * 8) + c4);
    }
    for (int i = tid; i < 256 * 2; i += TPB) {
        int k = i >> 1, c4 = i & 1;
        *(float4*)(sW2 + k * 8 + c4 * 4) =
            __ldg((const float4*)(W2 + (size_t)k * 256 + g * 8) + c4);
    }
    for (int i = tid; i < 128; i += TPB) sb3[i] = __ldg(&b3[g * 128 + i]);
    if (tid < 8)  sb1[tid] = __ldg(&b1[g * 8 + tid]);
    if (tid >= 8 && tid < 16) sb2[tid - 8] = __ldg(&b2[g * 8 + tid - 8]);
    for (int i = tid; i < 256; i += TPB) {
        int h = i >> 1, c = i & 1;
        smW[i] = __ldg(&mW[(size_t)h * 64 + g * 2 + c]);
        ssW[i] = __ldg(&sWp[(size_t)h * 64 + g * 2 + c]);
    }
    if (tid < 2)  smb_[tid] = __ldg(&mb[g * 2 + tid]);
    if (tid >= 2 && tid < 4) ssb[tid - 2] = __ldg(&sbp[g * 2 + tid - 2]);
    __syncthreads();

    // ---- RK state in epilogue layout ----
    // thread (wid, lane): r0 = wid*16 + (lane>>2); rows {r0, r0+8}; t4 = lane&3.
    // zbA/zbB[hl] = z[row, g*4+hl], redundant across the 4 t4 lanes.
    const int r0 = wid * 16 + (lane >> 2);
    const int t4 = lane & 3;
    float zbA[4], zbB[4];
    {
        float4 a = __ldg((const float4*)&z0[(size_t)(rowBase + r0) * 128 + g * 4]);
        float4 b = __ldg((const float4*)&z0[(size_t)(rowBase + r0 + 8) * 128 + g * 4]);
        zbA[0] = a.x; zbA[1] = a.y; zbA[2] = a.z; zbA[3] = a.w;
        zbB[0] = b.x; zbB[1] = b.y; zbB[2] = b.z; zbB[3] = b.w;
    }

    const size_t zOff  = (size_t)bb * (NH * 128);
    const size_t h1Off = (size_t)bb * (NBN * 128);

    unsigned ph = 0;
    unsigned cz = 0, c1 = 0, c2 = 0;

#pragma unroll 1
    for (int tau = 0; tau < NIVL; tau++) {
        float t0v = __ldg(&t[tau]);
        float t1v = __ldg(&t[tau + 1]);
        float dti = t1v - t0v;
        float hstep = dti * 0.25f;
        __syncthreads();
        for (int i = tid; i < 1024; i += TPB) {
            int rr = i >> 3, q = i & 7;
            const float* Xr = X + ((size_t)(rowBase + rr) * NTT + tau) * NIN;
            float4 x0 = __ldg((const float4*)Xr + q);
            float4 x1 = __ldg((const float4*)(Xr + NIN) + q);
            float* d = sDx + rr * 33 + q * 4;
            d[0] = (x1.x - x0.x) / dti;
            d[1] = (x1.y - x0.y) / dti;
            d[2] = (x1.z - x0.z) / dti;
            d[3] = (x1.w - x0.w) / dti;
        }
        __syncthreads();

        float dx0[8], dx1[8];
#pragma unroll
        for (int q = 0; q < 8; q++) {
            int i = (q >> 1) * 8 + t4 * 2 + (q & 1);
            dx0[q] = sDx[r0 * 33 + i];
            dx1[q] = sDx[(r0 + 8) * 33 + i];
        }

#pragma unroll 1
        for (int sub = 0; sub < 4; sub++) {
            float aA[4] = {0.f, 0.f, 0.f, 0.f}, aB[4] = {0.f, 0.f, 0.f, 0.f};
            float kpA[4] = {0.f, 0.f, 0.f, 0.f}, kpB[4] = {0.f, 0.f, 0.f, 0.f};
#pragma unroll 1
            for (int s = 0; s < 4; s++) {
                float cs = (s == 0) ? 0.f : ((s == 3) ? 1.f : 0.5f);

                // publish zc from epilogue registers (col-major [h][r])
                ++ph; int pz = ph & 1;
                {
                    float zA[4], zB[4];
#pragma unroll
                    for (int hl = 0; hl < 4; hl++) {
                        zA[hl] = fmaf(cs * hstep, kpA[hl], zbA[hl]);
                        zB[hl] = fmaf(cs * hstep, kpB[hl], zbB[hl]);
                    }
                    float vA = (t4 == 0) ? zA[0] : (t4 == 1) ? zA[1]
                             : (t4 == 2) ? zA[2] : zA[3];
                    float vB = (t4 == 0) ? zB[0] : (t4 == 1) ? zB[1]
                             : (t4 == 2) ? zB[2] : zB[3];
                    float* zc = &g_zc[pz][zOff + (size_t)(g * 4 + t4) * 128];
                    __stcg(zc + r0, vA);
                    __stcg(zc + r0 + 8, vB);
                }
                publish_cnt(myQz);
                ++cz;

                // stage 1 (waits z quarters internally)
                ++ph; int p1 = ph & 1;
                stage1(&g_zc[pz][zOff], sW1, sb1,
                       &g_h1[p1][h1Off + (size_t)(g * 8) * 128], sAct, tid,
                       qz, cz * 8);
                publish_cnt(myQ1);
                ++c1;

                // stage 2 -> A fragments (waits h1 quarters internally)
                ++ph; int p2 = ph & 1;
                stage2_frag(&g_h1[p1][h1Off], sW2, sb2,
                            (u32*)&g_fAhi[p2][bb][0], (u32*)&g_fAlo[p2][bb][0],
                            g, sAct, tid, q1, c1 * 8);
                publish_cnt(myQ2);
                ++c2;

                // ---- stage 3: mma.sync over fragments, quarter-gated loads ----
                float acc[16][4];
                {
                    const int c0b = t4 * 2;
#pragma unroll
                    for (int nt = 0; nt < 16; nt++) {
                        float bx = sb3[nt * 8 + c0b];
                        float by = sb3[nt * 8 + c0b + 1];
                        acc[nt][0] = bx; acc[nt][1] = by;
                        acc[nt][2] = bx; acc[nt][3] = by;
                    }
                }
                const uint4* fAh = &g_fAhi[p2][bb][0];
                const uint4* fAl = &g_fAlo[p2][bb][0];
                wait_cnt(&q2[0], c2 * 8);
                uint4 ah = __ldcg(fAh + (0 * 8 + wid) * 32 + lane);
                uint4 al = __ldcg(fAl + (0 * 8 + wid) * 32 + lane);
#pragma unroll 1
                for (int kt = 0; kt < 16; kt++) {
                    uint4 ahn, aln;
                    if (kt < 15) {
                        if (((kt + 1) & 3) == 0)
                            wait_cnt(&q2[(kt + 1) >> 2], c2 * 8);
                        ahn = __ldcg(fAh + ((kt + 1) * 8 + wid) * 32 + lane);
                        aln = __ldcg(fAl + ((kt + 1) * 8 + wid) * 32 + lane);
                    }
                    const uint4* bfr = sFragB + (kt * 16) * 32 + lane;
#pragma unroll
                    for (int nt = 0; nt < 16; nt++) {
                        uint4 b = bfr[nt * 32];
                        mma16816(acc[nt], ah, b.x, b.y);
                        mma16816(acc[nt], ah, b.z, b.w);
                        mma16816(acc[nt], al, b.x, b.y);
                    }
                    ah = ahn; al = aln;
                }

                // epilogue: tanh + dxdt contraction, butterfly reduce over t4
                float kq0[4] = {0.f, 0.f, 0.f, 0.f};
                float kq1[4] = {0.f, 0.f, 0.f, 0.f};
#pragma unroll
                for (int nt = 0; nt < 16; nt++) {
                    int hl = nt >> 2, q = (nt & 3) * 2;
                    float y;
                    y = fast_tanh(acc[nt][0]); kq0[hl] = fmaf(y, dx0[q],     kq0[hl]);
                    y = fast_tanh(acc[nt][1]); kq0[hl] = fmaf(y, dx0[q + 1], kq0[hl]);
                    y = fast_tanh(acc[nt][2]); kq1[hl] = fmaf(y, dx1[q],     kq1[hl]);
                    y = fast_tanh(acc[nt][3]); kq1[hl] = fmaf(y, dx1[q + 1], kq1[hl]);
                }
#pragma unroll
                for (int hl = 0; hl < 4; hl++) {
                    kq0[hl] += __shfl_xor_sync(0xffffffffu, kq0[hl], 1);
                    kq0[hl] += __shfl_xor_sync(0xffffffffu, kq0[hl], 2);
                    kq1[hl] += __shfl_xor_sync(0xffffffffu, kq1[hl], 1);
                    kq1[hl] += __shfl_xor_sync(0xffffffffu, kq1[hl], 2);
                }
                float ws = (s == 0 || s == 3) ? 1.f : 2.f;
#pragma unroll
                for (int hl = 0; hl < 4; hl++) {
                    aA[hl] = fmaf(ws, kq0[hl], aA[hl]);
                    aB[hl] = fmaf(ws, kq1[hl], aB[hl]);
                    kpA[hl] = kq0[hl];
                    kpB[hl] = kq1[hl];
                }
            }
            float h6 = hstep / 6.0f;
#pragma unroll
            for (int hl = 0; hl < 4; hl++) {
                zbA[hl] = fmaf(h6, aA[hl], zbA[hl]);
                zbB[hl] = fmaf(h6, aB[hl], zbB[hl]);
            }
        }

        // ---- interval end: publish final z, output heads ----
        ++ph; int pz = ph & 1;
        {
            float vA = (t4 == 0) ? zbA[0] : (t4 == 1) ? zbA[1]
                     : (t4 == 2) ? zbA[2] : zbA[3];
            float vB = (t4 == 0) ? zbB[0] : (t4 == 1) ? zbB[1]
                     : (t4 == 2) ? zbB[2] : zbB[3];
            float* zc = &g_zc[pz][zOff + (size_t)(g * 4 + t4) * 128];
            __stcg(zc + r0, vA);
            __stcg(zc + r0 + 8, vB);
        }
        publish_cnt(myQz);
        ++cz;
        wait_cnt(&qz[0], cz * 8);
        wait_cnt(&qz[1], cz * 8);
        wait_cnt(&qz[2], cz * 8);
        wait_cnt(&qz[3], cz * 8);
        {
            const int r  = tid & 127;
            const int hh = tid >> 7;
            const int b  = rowBase + r;
            const float* wsel = hh ? ssW : smW;
            float acc0 = hh ? ssb[0] : smb_[0];
            float acc1 = hh ? ssb[1] : smb_[1];
            const float* zbase = &g_zc[pz][zOff];
#pragma unroll 8
            for (int h = 0; h < 128; h++) {
                float zv = __ldcg(zbase + (size_t)h * 128 + r);
                acc0 = fmaf(zv, wsel[h * 2 + 0], acc0);
                acc1 = fmaf(zv, wsel[h * 2 + 1], acc1);
            }
            if (hh) { acc0 = softplus_f(acc0); acc1 = softplus_f(acc1); }
            float* dst = out + (hh ? (size_t)NBATCH * NIVL * NOUT : 0)
                         + ((size_t)b * NIVL + tau) * NOUT + g * 2;
            dst[0] = acc0;
            dst[1] = acc1;
        }
    }

    // ---- end-of-kernel reset for deterministic graph replay ----
    gbar_val(bb, 1u);
    if (tid == 0 && g == 0) {
#pragma unroll
        for (int q = 0; q < 4; q++) {
            g_qz[bb][q].v = 0u;
            g_q1[bb][q].v = 0u;
            g_q2[bb][q].v = 0u;
        }
    }
    gbar_val(bb, 0u);
}

extern "C" void kernel_launch(void* const* d_in, const int* in_sizes, int n_in,
                              void* d_out, int out_size) {
    const float* t   = (const float*)d_in[0];
    const float* z0  = (const float*)d_in[1];
    const float* X   = (const float*)d_in[2];
    const float* W1  = (const float*)d_in[3];
    const float* b1  = (const float*)d_in[4];
    const float* W2  = (const float*)d_in[5];
    const float* b2  = (const float*)d_in[6];
    const float* W3  = (const float*)d_in[7];
    const float* b3  = (const float*)d_in[8];
    const float* mW  = (const float*)d_in[9];
    const float* mb  = (const float*)d_in[10];
    const float* sW  = (const float*)d_in[11];
    const float* sb  = (const float*)d_in[12];
    float* out = (float*)d_out;

    cudaFuncSetAttribute(cde_persistent,
                         cudaFuncAttributeMaxDynamicSharedMemorySize, SMEM_BYTES);
    cde_persistent<<<GRID_CTAS, TPB, SMEM_BYTES>>>(t, z0, X, W1, b1, W2, b2,
                                                   W3, b3, mW, mb, sW, sb, out);
}

// round 9
// speedup vs baseline: 1.2102x; 1.2102x over previous
#include <cuda_runtime.h>
#include <cuda_bf16.h>

typedef unsigned long long u64;
typedef unsigned int u32;

#define NBATCH 512
#define NTT    257
#define NIVL   256
#define NIN    32
#define NH     128
#define NBN    256
#define NOUT   64
#define GRID_CTAS 256
#define TPB    128
#define NGRP   64        // CTAs per bb group

// ---- shared memory byte offsets ----
#define SM_FRAGB 0       // [16 kt][8 nt][32 lane] uint4 = 64KB
#define SM_W1    65536   // [128 k][4 c] f32 = 2KB
#define SM_W2    67584   // [256 k][4 c] f32 = 4KB
#define SM_B3    71680   // [64] f32
#define SM_B1    71936   // [4]
#define SM_B2    71952   // [4]
#define SM_MW    71968   // [128] f32 (mean head col g)
#define SM_SW    72480   // [128] f32 (std head col g)
#define SM_MBS   72992   // [2] f32 (mb[g], sbp[g]) + pad
#define SM_ACT   73024   // 2 x 2048 f32 staging (16KB)
#define SMEM_BYTES 89408

// ---- global scratch (parity double-buffered) ----
__device__ float g_zc[2][4 * NH * 128];    // col-major [h][r] per bb
__device__ float g_h1[2][4 * NBN * 128];   // col-major [c][r] per bb
__device__ uint4 g_fAhi[2][4][4096];       // A frags [kt*8+mt][lane]
__device__ uint4 g_fAlo[2][4][4096];

// ---- arrive counters: one padded line per (bb, stage-type) ----
struct PadCnt { unsigned v; unsigned pad[127]; };
__device__ PadCnt g_ccz[4];
__device__ PadCnt g_cc1[4];
__device__ PadCnt g_cc2[4];

struct PadU { unsigned v; unsigned pad[31]; };
__device__ PadU g_cnt[4];
__device__ PadU g_rel[4];

// ---- f32x2 helpers ----
__device__ __forceinline__ u64 pack2(float x, float y) {
    u64 r;
    asm("mov.b64 %0, {%1, %2};" : "=l"(r) : "f"(x), "f"(y));
    return r;
}
__device__ __forceinline__ float2 unpack2(u64 v) {
    float2 r;
    asm("mov.b64 {%0, %1}, %2;" : "=f"(r.x), "=f"(r.y) : "l"(v));
    return r;
}
__device__ __forceinline__ void fma2(u64& d, u64 a, u64 b) {
    asm("fma.rn.f32x2 %0, %1, %2, %0;" : "+l"(d) : "l"(a), "l"(b));
}

__device__ __forceinline__ float fast_tanh(float x) {
    float e;
    asm("ex2.approx.f32 %0, %1;" : "=f"(e) : "f"(x * 2.8853900817779268f));
    float r;
    asm("rcp.approx.f32 %0, %1;" : "=f"(r) : "f"(e + 1.0f));
    return fmaf(-2.0f, r, 1.0f);
}
__device__ __forceinline__ float softplus_f(float x) {
    return fmaxf(x, 0.0f) + log1pf(expf(-fabsf(x)));
}

__device__ __forceinline__ void mma16816(float* c, uint4 a, u32 b0, u32 b1) {
    asm volatile(
        "mma.sync.aligned.m16n8k16.row.col.f32.bf16.bf16.f32 "
        "{%0,%1,%2,%3}, {%4,%5,%6,%7}, {%8,%9}, {%0,%1,%2,%3};"
        : "+f"(c[0]), "+f"(c[1]), "+f"(c[2]), "+f"(c[3])
        : "r"(a.x), "r"(a.y), "r"(a.z), "r"(a.w), "r"(b0), "r"(b1));
}

__device__ __forceinline__ void bf_split(float x, unsigned short& h, unsigned short& l) {
    __nv_bfloat16 bh = __float2bfloat16_rn(x);
    __nv_bfloat16 bl = __float2bfloat16_rn(x - __bfloat162float(bh));
    h = __bfloat16_as_ushort(bh);
    l = __bfloat16_as_ushort(bl);
}

// ---- counter publish / wait ----
__device__ __forceinline__ void publish_cnt(PadCnt* c) {
    __syncthreads();
    if (threadIdx.x == 0) {
        asm volatile("red.release.gpu.global.add.u32 [%0], %1;"
                     :: "l"(&c->v), "r"(1u) : "memory");
    }
}
__device__ __forceinline__ void wait_cnt(PadCnt* c, unsigned target) {
    if (threadIdx.x == 0) {
        unsigned v;
        do {
            asm volatile("ld.acquire.gpu.u32 %0, [%1];"
                         : "=r"(v) : "l"(&c->v) : "memory");
        } while ((int)(v - target) < 0);
    }
    __syncthreads();
}

// ---- legacy group barrier (end-of-kernel reset only; 64 CTAs/group) ----
__device__ __forceinline__ void gbar_val(int grp, unsigned target) {
    __syncthreads();
    if (threadIdx.x == 0) {
        __threadfence();
        unsigned old = atomicAdd(&g_cnt[grp].v, 1u);
        if (old == (NGRP - 1u)) {
            g_cnt[grp].v = 0u;
            asm volatile("st.release.gpu.u32 [%0], %1;"
                         :: "l"(&g_rel[grp].v), "r"(target) : "memory");
        } else {
            unsigned v;
            do {
                asm volatile("ld.acquire.gpu.u32 %0, [%1];"
                             : "=r"(v) : "l"(&g_rel[grp].v) : "memory");
            } while (v != target);
        }
    }
    __syncthreads();
}

// ---- MLP core: acc over gin_cm[KT][128] with per-CTA 4-col weight slice ----
template <int KT>
__device__ __forceinline__ float4 mlp_core(const float* __restrict__ gin_cm,
                                           const float* __restrict__ sW,
                                           const float* __restrict__ sb,
                                           float* __restrict__ sAct, int tid) {
    u64 acc0 = pack2(sb[0], sb[1]);
    u64 acc1 = pack2(sb[2], sb[3]);

    const float4* src = (const float4*)gin_cm;
    float4 v0 = __ldcg(src + 0 * 128 + tid);
    float4 v1 = __ldcg(src + 1 * 128 + tid);
    float4 v2 = __ldcg(src + 2 * 128 + tid);
    float4 v3 = __ldcg(src + 3 * 128 + tid);

    const int NCH = KT / 16;
#pragma unroll 1
    for (int kc = 0; kc < NCH; kc++) {
        float4* buf4 = (float4*)(sAct + (kc & 1) * 2048);
        buf4[0 * 128 + tid] = v0;
        buf4[1 * 128 + tid] = v1;
        buf4[2 * 128 + tid] = v2;
        buf4[3 * 128 + tid] = v3;
        __syncthreads();
        if (kc + 1 < NCH) {
            const float4* sn = src + (kc + 1) * 512;
            v0 = __ldcg(sn + 0 * 128 + tid);
            v1 = __ldcg(sn + 1 * 128 + tid);
            v2 = __ldcg(sn + 2 * 128 + tid);
            v3 = __ldcg(sn + 3 * 128 + tid);
        }
        const float* buf = sAct + (kc & 1) * 2048;
        const float* wk  = sW + kc * 64;
#pragma unroll
        for (int k = 0; k < 16; k++) {
            float a = buf[k * 128 + tid];
            u64 aa  = pack2(a, a);
            ulonglong2 wv = *(const ulonglong2*)(wk + k * 4);
            fma2(acc0, aa, wv.x);
            fma2(acc1, aa, wv.y);
        }
        __syncthreads();
    }
    float2 u0 = unpack2(acc0), u1 = unpack2(acc1);
    return make_float4(u0.x, u0.y, u1.x, u1.y);
}

// ================= persistent kernel =================
__global__ void __launch_bounds__(TPB, 2)
cde_persistent(const float* __restrict__ t, const float* __restrict__ z0,
               const float* __restrict__ X,
               const float* __restrict__ W1, const float* __restrict__ b1,
               const float* __restrict__ W2, const float* __restrict__ b2,
               const float* __restrict__ W3, const float* __restrict__ b3,
               const float* __restrict__ mW, const float* __restrict__ mb,
               const float* __restrict__ sWp, const float* __restrict__ sbp,
               float* __restrict__ out) {
    extern __shared__ char smb[];
    uint4* sFragB = (uint4*)(smb + SM_FRAGB);
    float* sW1  = (float*)(smb + SM_W1);
    float* sW2  = (float*)(smb + SM_W2);
    float* sb3  = (float*)(smb + SM_B3);
    float* sb1  = (float*)(smb + SM_B1);
    float* sb2  = (float*)(smb + SM_B2);
    float* smW  = (float*)(smb + SM_MW);
    float* ssW  = (float*)(smb + SM_SW);
    float* sMBS = (float*)(smb + SM_MBS);
    float* sAct = (float*)(smb + SM_ACT);

    const int tid  = threadIdx.x;
    const int wid  = tid >> 5;
    const int lane = tid & 31;
    const int bb   = blockIdx.x >> 6;      // 0..3
    const int g    = blockIdx.x & 63;      // 0..63 column group
    const int rowBase = bb * 128;

    // ---- init: W3 slice (64 cols) -> B fragments (hi/lo) in smem ----
    for (int i = tid; i < 16 * 8 * 32; i += TPB) {
        int ln = i & 31, nt = (i >> 5) & 7, kt = i >> 8;
        int nl = nt * 8 + (ln >> 2);
        int k0 = kt * 16 + (ln & 3) * 2;
        const float* wp = W3 + (size_t)k0 * 4096 + g * 64 + nl;
        unsigned short h0, h1, h8, h9, l0, l1, l8, l9;
        bf_split(wp[0],        h0, l0);
        bf_split(wp[4096],     h1, l1);
        bf_split(wp[8 * 4096], h8, l8);
        bf_split(wp[9 * 4096], h9, l9);
        uint4 v;
        v.x = ((u32)h1 << 16) | h0;
        v.y = ((u32)h9 << 16) | h8;
        v.z = ((u32)l1 << 16) | l0;
        v.w = ((u32)l9 << 16) | l8;
        sFragB[i] = v;
    }
    for (int k = tid; k < 128; k += TPB)
        *(float4*)(sW1 + k * 4) = __ldg((const float4*)(W1 + (size_t)k * 256 + g * 4));
    for (int k = tid; k < 256; k += TPB)
        *(float4*)(sW2 + k * 4) = __ldg((const float4*)(W2 + (size_t)k * 256 + g * 4));
    for (int i = tid; i < 64; i += TPB) sb3[i] = __ldg(&b3[g * 64 + i]);
    if (tid < 4)  sb1[tid] = __ldg(&b1[g * 4 + tid]);
    if (tid >= 4 && tid < 8) sb2[tid - 4] = __ldg(&b2[g * 4 + tid - 4]);
    for (int h = tid; h < 128; h += TPB) {
        smW[h] = __ldg(&mW[(size_t)h * 64 + g]);
        ssW[h] = __ldg(&sWp[(size_t)h * 64 + g]);
    }
    if (tid == 8) sMBS[0] = __ldg(&mb[g]);
    if (tid == 9) sMBS[1] = __ldg(&sbp[g]);
    __syncthreads();

    // ---- RK state in epilogue layout ----
    // warp wid handles m-tiles {2wid, 2wid+1} (rows 32wid..+32).
    // thread rows: rows[ridx] = 32wid + 16*(ridx>>1) + (lane>>2) + 8*(ridx&1)
    const int rsub = lane >> 2;
    const int t4   = lane & 3;
    int rows[4];
    rows[0] = wid * 32 + rsub;
    rows[1] = wid * 32 + rsub + 8;
    rows[2] = wid * 32 + rsub + 16;
    rows[3] = wid * 32 + rsub + 24;

    float zb[4][2];
#pragma unroll
    for (int ridx = 0; ridx < 4; ridx++) {
        float2 z = __ldg((const float2*)&z0[(size_t)(rowBase + rows[ridx]) * 128 + g * 2]);
        zb[ridx][0] = z.x;
        zb[ridx][1] = z.y;
    }

    const size_t zOff  = (size_t)bb * (NH * 128);
    const size_t h1Off = (size_t)bb * (NBN * 128);

    unsigned ph = 0;
    unsigned cz = 0, c1 = 0, c2 = 0;

    // stage-2 fragment slot constants (cols c = g*4 + j)
    const int fr_r   = tid;              // row = tid (0..127)
    const int fr_mt  = fr_r >> 4;
    const int fr_rit = fr_r & 15;
    const int fr_lane = (fr_rit & 7) * 4 + ((g & 3) & 1) * 2;
    const int fr_reg  = (fr_rit >> 3) + 2 * ((g & 3) >> 1);
    const int fr_base = (((g >> 2) * 8 + fr_mt) * 32 + fr_lane) * 4 + fr_reg;

#pragma unroll 1
    for (int tau = 0; tau < NIVL; tau++) {
        float t0v = __ldg(&t[tau]);
        float t1v = __ldg(&t[tau + 1]);
        float dti = t1v - t0v;
        float hstep = dti * 0.25f;

        // dxdt straight into registers (per-thread i-slice, 4 rows)
        float dxm[4][8];
#pragma unroll
        for (int ridx = 0; ridx < 4; ridx++) {
            const float* Xr = X + ((size_t)(rowBase + rows[ridx]) * NTT + tau) * NIN;
#pragma unroll
            for (int blk = 0; blk < 4; blk++) {
                float2 x0 = __ldg((const float2*)(Xr + blk * 8 + t4 * 2));
                float2 x1 = __ldg((const float2*)(Xr + NIN + blk * 8 + t4 * 2));
                dxm[ridx][blk * 2 + 0] = (x1.x - x0.x) / dti;
                dxm[ridx][blk * 2 + 1] = (x1.y - x0.y) / dti;
            }
        }

#pragma unroll 1
        for (int sub = 0; sub < 4; sub++) {
            float aq[4][2] = {{0.f,0.f},{0.f,0.f},{0.f,0.f},{0.f,0.f}};
            float kp[4][2] = {{0.f,0.f},{0.f,0.f},{0.f,0.f},{0.f,0.f}};
#pragma unroll 1
            for (int s = 0; s < 4; s++) {
                float cs = (s == 0) ? 0.f : ((s == 3) ? 1.f : 0.5f);

                // publish zc from registers (col-major [h][r]); t4<2 lanes store col t4
                ++ph; int pz = ph & 1;
                if (t4 < 2) {
                    float* zc = &g_zc[pz][zOff + (size_t)(g * 2 + t4) * 128];
#pragma unroll
                    for (int ridx = 0; ridx < 4; ridx++) {
                        float zv = fmaf(cs * hstep, kp[ridx][t4], zb[ridx][t4]);
                        __stcg(zc + rows[ridx], zv);
                    }
                }
                publish_cnt(&g_ccz[bb]);
                ++cz;
                wait_cnt(&g_ccz[bb], cz * NGRP);

                // stage 1: 4 h1 cols (col-major out)
                ++ph; int p1 = ph & 1;
                {
                    float4 o = mlp_core<128>(&g_zc[pz][zOff], sW1, sb1, sAct, tid);
                    float* gout = &g_h1[p1][h1Off + (size_t)(g * 4) * 128];
                    __stcg(gout + 0 * 128 + tid, fmaxf(o.x, 0.f));
                    __stcg(gout + 1 * 128 + tid, fmaxf(o.y, 0.f));
                    __stcg(gout + 2 * 128 + tid, fmaxf(o.z, 0.f));
                    __stcg(gout + 3 * 128 + tid, fmaxf(o.w, 0.f));
                }
                publish_cnt(&g_cc1[bb]);
                ++c1;
                wait_cnt(&g_cc1[bb], c1 * NGRP);

                // stage 2: 4 h2 cols -> bf16 hi/lo A-fragments
                ++ph; int p2 = ph & 1;
                {
                    float4 o = mlp_core<256>(&g_h1[p1][h1Off], sW2, sb2, sAct, tid);
                    float o0 = fmaxf(o.x, 0.f), o1 = fmaxf(o.y, 0.f);
                    float o2 = fmaxf(o.z, 0.f), o3 = fmaxf(o.w, 0.f);
                    unsigned short h0, h1v, h2v, h3v, l0, l1v, l2v, l3v;
                    bf_split(o0, h0, l0);  bf_split(o1, h1v, l1v);
                    bf_split(o2, h2v, l2v); bf_split(o3, h3v, l3v);
                    u32* fHi = (u32*)&g_fAhi[p2][bb][0];
                    u32* fLo = (u32*)&g_fAlo[p2][bb][0];
                    __stcg(&fHi[fr_base],     ((u32)h1v << 16) | h0);
                    __stcg(&fHi[fr_base + 4], ((u32)h3v << 16) | h2v);
                    __stcg(&fLo[fr_base],     ((u32)l1v << 16) | l0);
                    __stcg(&fLo[fr_base + 4], ((u32)l3v << 16) | l2v);
                }
                publish_cnt(&g_cc2[bb]);
                ++c2;
                wait_cnt(&g_cc2[bb], c2 * NGRP);

                // ---- stage 3: mma.sync, 2 m-tiles per warp ----
                float acc[2][8][4];
#pragma unroll
                for (int nt = 0; nt < 8; nt++) {
                    float bx = sb3[nt * 8 + t4 * 2];
                    float by = sb3[nt * 8 + t4 * 2 + 1];
#pragma unroll
                    for (int mti = 0; mti < 2; mti++) {
                        acc[mti][nt][0] = bx; acc[mti][nt][1] = by;
                        acc[mti][nt][2] = bx; acc[mti][nt][3] = by;
                    }
                }
                const uint4* fAh = &g_fAhi[p2][bb][0];
                const uint4* fAl = &g_fAlo[p2][bb][0];
                uint4 a0h = __ldcg(fAh + (0 * 8 + 2 * wid + 0) * 32 + lane);
                uint4 a0l = __ldcg(fAl + (0 * 8 + 2 * wid + 0) * 32 + lane);
                uint4 a1h = __ldcg(fAh + (0 * 8 + 2 * wid + 1) * 32 + lane);
                uint4 a1l = __ldcg(fAl + (0 * 8 + 2 * wid + 1) * 32 + lane);
#pragma unroll 1
                for (int kt = 0; kt < 16; kt++) {
                    uint4 n0h, n0l, n1h, n1l;
                    if (kt < 15) {
                        n0h = __ldcg(fAh + ((kt + 1) * 8 + 2 * wid + 0) * 32 + lane);
                        n0l = __ldcg(fAl + ((kt + 1) * 8 + 2 * wid + 0) * 32 + lane);
                        n1h = __ldcg(fAh + ((kt + 1) * 8 + 2 * wid + 1) * 32 + lane);
                        n1l = __ldcg(fAl + ((kt + 1) * 8 + 2 * wid + 1) * 32 + lane);
                    }
                    const uint4* bfr = sFragB + (kt * 8) * 32 + lane;
#pragma unroll
                    for (int nt = 0; nt < 8; nt++) {
                        uint4 b = bfr[nt * 32];
                        mma16816(acc[0][nt], a0h, b.x, b.y);
                        mma16816(acc[0][nt], a0h, b.z, b.w);
                        mma16816(acc[0][nt], a0l, b.x, b.y);
                        mma16816(acc[1][nt], a1h, b.x, b.y);
                        mma16816(acc[1][nt], a1h, b.z, b.w);
                        mma16816(acc[1][nt], a1l, b.x, b.y);
                    }
                    a0h = n0h; a0l = n0l; a1h = n1h; a1l = n1l;
                }

                // epilogue: tanh + dxdt contraction, butterfly over t4
                float kq[4][2] = {{0.f,0.f},{0.f,0.f},{0.f,0.f},{0.f,0.f}};
#pragma unroll
                for (int mti = 0; mti < 2; mti++) {
#pragma unroll
                    for (int nt = 0; nt < 8; nt++) {
                        int hcol = nt >> 2, qb = (nt & 3) * 2;
                        int r0i = mti * 2, r1i = mti * 2 + 1;
                        float y;
                        y = fast_tanh(acc[mti][nt][0]);
                        kq[r0i][hcol] = fmaf(y, dxm[r0i][qb],     kq[r0i][hcol]);
                        y = fast_tanh(acc[mti][nt][1]);
                        kq[r0i][hcol] = fmaf(y, dxm[r0i][qb + 1], kq[r0i][hcol]);
                        y = fast_tanh(acc[mti][nt][2]);
                        kq[r1i][hcol] = fmaf(y, dxm[r1i][qb],     kq[r1i][hcol]);
                        y = fast_tanh(acc[mti][nt][3]);
                        kq[r1i][hcol] = fmaf(y, dxm[r1i][qb + 1], kq[r1i][hcol]);
                    }
                }
#pragma unroll
                for (int ridx = 0; ridx < 4; ridx++) {
#pragma unroll
                    for (int h = 0; h < 2; h++) {
                        kq[ridx][h] += __shfl_xor_sync(0xffffffffu, kq[ridx][h], 1);
                        kq[ridx][h] += __shfl_xor_sync(0xffffffffu, kq[ridx][h], 2);
                    }
                }
                float ws = (s == 0 || s == 3) ? 1.f : 2.f;
#pragma unroll
                for (int ridx = 0; ridx < 4; ridx++) {
#pragma unroll
                    for (int h = 0; h < 2; h++) {
                        aq[ridx][h] = fmaf(ws, kq[ridx][h], aq[ridx][h]);
                        kp[ridx][h] = kq[ridx][h];
                    }
                }
            }
            float h6 = hstep / 6.0f;
#pragma unroll
            for (int ridx = 0; ridx < 4; ridx++) {
#pragma unroll
                for (int h = 0; h < 2; h++)
                    zb[ridx][h] = fmaf(h6, aq[ridx][h], zb[ridx][h]);
            }
        }

        // ---- interval end: publish final z, output heads ----
        ++ph; int pz = ph & 1;
        if (t4 < 2) {
            float* zc = &g_zc[pz][zOff + (size_t)(g * 2 + t4) * 128];
#pragma unroll
            for (int ridx = 0; ridx < 4; ridx++)
                __stcg(zc + rows[ridx], zb[ridx][t4]);
        }
        publish_cnt(&g_ccz[bb]);
        ++cz;
        wait_cnt(&g_ccz[bb], cz * NGRP);
        {
            const int row = tid;
            const int b   = rowBase + row;
            float am = sMBS[0], as = sMBS[1];
            const float* zbase = &g_zc[pz][zOff];
#pragma unroll 8
            for (int h = 0; h < 128; h++) {
                float zv = __ldcg(zbase + (size_t)h * 128 + row);
                am = fmaf(zv, smW[h], am);
                as = fmaf(zv, ssW[h], as);
            }
            as = softplus_f(as);
            out[((size_t)b * NIVL + tau) * NOUT + g] = am;
            out[(size_t)NBATCH * NIVL * NOUT + ((size_t)b * NIVL + tau) * NOUT + g] = as;
        }
    }

    // ---- end-of-kernel reset for deterministic graph replay ----
    gbar_val(bb, 1u);
    if (tid == 0 && g == 0) {
        g_ccz[bb].v = 0u;
        g_cc1[bb].v = 0u;
        g_cc2[bb].v = 0u;
    }
    gbar_val(bb, 0u);
}

extern "C" void kernel_launch(void* const* d_in, const int* in_sizes, int n_in,
                              void* d_out, int out_size) {
    const float* t   = (const float*)d_in[0];
    const float* z0  = (const float*)d_in[1];
    const float* X   = (const float*)d_in[2];
    const float* W1  = (const float*)d_in[3];
    const float* b1  = (const float*)d_in[4];
    const float* W2  = (const float*)d_in[5];
    const float* b2  = (const float*)d_in[6];
    const float* W3  = (const float*)d_in[7];
    const float* b3  = (const float*)d_in[8];
    const float* mW  = (const float*)d_in[9];
    const float* mb  = (const float*)d_in[10];
    const float* sW  = (const float*)d_in[11];
    const float* sb  = (const float*)d_in[12];
    float* out = (float*)d_out;

    cudaFuncSetAttribute(cde_persistent,
                         cudaFuncAttributeMaxDynamicSharedMemorySize, SMEM_BYTES);
    cde_persistent<<<GRID_CTAS, TPB, SMEM_BYTES>>>(t, z0, X, W1, b1, W2, b2,
                                                   W3, b3, mW, mb, sW, sb, out);
}